// round 15
// baseline (speedup 1.0000x reference)
#include <cuda_runtime.h>
#include <cuda_bf16.h>

#define F        128
#define F4       32          // F/4
#define NMAX     100000
#define EMAX     1600000
#define BM       64          // rows per GEMM tile
#define NSM      148
#define SCAN_BLK 1024
#define NBMAX    ((NMAX + SCAN_BLK - 1) / SCAN_BLK)

// Scratch (allocation-free rule: device globals are the sanctioned path)
__device__ float4 g_agg[NMAX * F4];          // aggregate (pre-divided by deg)
__device__ int    g_cnt[NMAX];               // degree counters
__device__ int    g_rowptr[NMAX + 1];        // CSR row pointers
__device__ int    g_woff[NMAX];              // working offsets for bucket scatter
__device__ int    g_bsum[NBMAX];             // scan block sums
__device__ int2   g_epair[EMAX];             // CSR-ordered {col, val_bits}

// packed f32x2 helpers (Blackwell FFMA2)
__device__ __forceinline__ void fma2(unsigned long long& d,
                                     unsigned long long a,
                                     unsigned long long b) {
    asm("fma.rn.f32x2 %0, %1, %2, %0;" : "+l"(d) : "l"(a), "l"(b));
}
__device__ __forceinline__ unsigned long long pack2(float lo, float hi) {
    unsigned long long u;
    asm("mov.b64 %0, {%1, %2};" : "=l"(u) : "f"(lo), "f"(hi));
    return u;
}
__device__ __forceinline__ float2 unpack2(unsigned long long u) {
    float lo, hi;
    asm("mov.b64 {%0, %1}, %2;" : "=f"(lo), "=f"(hi) : "l"(u));
    return make_float2(lo, hi);
}

// ---------------------------------------------------------------------------
// Kernel 0: zero the degree counters
// ---------------------------------------------------------------------------
__global__ void zero_cnt_kernel(int n_nodes) {
    int i = blockIdx.x * blockDim.x + threadIdx.x;
    if (i < n_nodes) g_cnt[i] = 0;
}

// ---------------------------------------------------------------------------
// Kernel 1: count degrees (2 edges/thread)
// ---------------------------------------------------------------------------
__global__ void count_kernel(const int* __restrict__ row, int E) {
    int e = (blockIdx.x * blockDim.x + threadIdx.x) * 2;
    if (e + 1 < E) {
        int2 r2 = *(const int2*)&row[e];
        atomicAdd(&g_cnt[r2.x], 1);
        atomicAdd(&g_cnt[r2.y], 1);
    } else if (e < E) {
        atomicAdd(&g_cnt[row[e]], 1);
    }
}

// ---------------------------------------------------------------------------
// Kernels 2-4: exclusive scan of degrees -> row_ptr (3-stage)
// ---------------------------------------------------------------------------
__global__ void scan1_kernel(int n_nodes) {
    __shared__ int sh[SCAN_BLK];
    int gi = blockIdx.x * SCAN_BLK + threadIdx.x;
    int v  = (gi < n_nodes) ? g_cnt[gi] : 0;
    sh[threadIdx.x] = v;
    __syncthreads();
#pragma unroll
    for (int off = 1; off < SCAN_BLK; off <<= 1) {
        int t = (threadIdx.x >= off) ? sh[threadIdx.x - off] : 0;
        __syncthreads();
        sh[threadIdx.x] += t;
        __syncthreads();
    }
    if (gi < n_nodes) g_cnt[gi] = sh[threadIdx.x] - v;       // exclusive within block
    if (threadIdx.x == SCAN_BLK - 1) g_bsum[blockIdx.x] = sh[threadIdx.x];
}

__global__ void scan2_kernel(int nb) {                        // one block, nb <= 1024
    __shared__ int sh[SCAN_BLK];
    int v = (threadIdx.x < nb) ? g_bsum[threadIdx.x] : 0;
    sh[threadIdx.x] = v;
    __syncthreads();
#pragma unroll
    for (int off = 1; off < SCAN_BLK; off <<= 1) {
        int t = (threadIdx.x >= off) ? sh[threadIdx.x - off] : 0;
        __syncthreads();
        sh[threadIdx.x] += t;
        __syncthreads();
    }
    if (threadIdx.x < nb) g_bsum[threadIdx.x] = sh[threadIdx.x] - v;  // exclusive
}

__global__ void scan3_kernel(int n_nodes, int E) {
    int gi = blockIdx.x * SCAN_BLK + threadIdx.x;
    if (gi < n_nodes) {
        int r = g_cnt[gi] + g_bsum[blockIdx.x];
        g_rowptr[gi] = r;
        g_woff[gi]   = r;
    }
    if (gi == 0) g_rowptr[n_nodes] = E;
}

// ---------------------------------------------------------------------------
// Kernel 5: bucket-permute {col, val} into CSR order (2 edges/thread)
// ---------------------------------------------------------------------------
__global__ void bucket_kernel(const int*   __restrict__ row,
                              const int*   __restrict__ col,
                              const float* __restrict__ val,
                              int E) {
    int e = (blockIdx.x * blockDim.x + threadIdx.x) * 2;
    if (e + 1 < E) {
        int2   r2 = *(const int2*)&row[e];
        int2   c2 = *(const int2*)&col[e];
        float2 v2 = *(const float2*)&val[e];
        int p0 = atomicAdd(&g_woff[r2.x], 1);
        g_epair[p0] = make_int2(c2.x, __float_as_int(v2.x));
        int p1 = atomicAdd(&g_woff[r2.y], 1);
        g_epair[p1] = make_int2(c2.y, __float_as_int(v2.y));
    } else if (e < E) {
        int pos = atomicAdd(&g_woff[row[e]], 1);
        g_epair[pos] = make_int2(col[e], __float_as_int(val[e]));
    }
}

// ---------------------------------------------------------------------------
// Kernel 6: warp-per-node gather aggregate, 4-way unrolled (MLP=4).
//   Aggregate is latency-bound (fp16 byte-halving was neutral-negative):
//   4 independent shfl->gather->FMA chains per iteration to cover L2 latency.
// ---------------------------------------------------------------------------
__global__ void aggregate_kernel(const float4* __restrict__ x4, int n_nodes) {
    int nid  = (blockIdx.x * blockDim.x + threadIdx.x) >> 5;
    int lane = threadIdx.x & 31;
    if (nid >= n_nodes) return;

    int s    = g_rowptr[nid];
    int tEnd = g_rowptr[nid + 1];

    float4 a0 = make_float4(0.f, 0.f, 0.f, 0.f);
    float4 a1 = make_float4(0.f, 0.f, 0.f, 0.f);
    float4 a2 = make_float4(0.f, 0.f, 0.f, 0.f);
    float4 a3 = make_float4(0.f, 0.f, 0.f, 0.f);

    for (int base = s; base < tEnd; base += 32) {
        int e = base + lane;
        int2 p = (e < tEnd) ? g_epair[e] : make_int2(0, 0);
        int cnt = min(32, tEnd - base);
        int j = 0;
        for (; j + 4 <= cnt; j += 4) {
            int   c0 = __shfl_sync(0xffffffffu, p.x, j);
            float v0 = __int_as_float(__shfl_sync(0xffffffffu, p.y, j));
            int   c1 = __shfl_sync(0xffffffffu, p.x, j + 1);
            float v1 = __int_as_float(__shfl_sync(0xffffffffu, p.y, j + 1));
            int   c2 = __shfl_sync(0xffffffffu, p.x, j + 2);
            float v2 = __int_as_float(__shfl_sync(0xffffffffu, p.y, j + 2));
            int   c3 = __shfl_sync(0xffffffffu, p.x, j + 3);
            float v3 = __int_as_float(__shfl_sync(0xffffffffu, p.y, j + 3));
            float4 x0 = x4[(long long)c0 * F4 + lane];
            float4 x1 = x4[(long long)c1 * F4 + lane];
            float4 x2 = x4[(long long)c2 * F4 + lane];
            float4 x3 = x4[(long long)c3 * F4 + lane];
            a0.x += v0 * x0.x; a0.y += v0 * x0.y;
            a0.z += v0 * x0.z; a0.w += v0 * x0.w;
            a1.x += v1 * x1.x; a1.y += v1 * x1.y;
            a1.z += v1 * x1.z; a1.w += v1 * x1.w;
            a2.x += v2 * x2.x; a2.y += v2 * x2.y;
            a2.z += v2 * x2.z; a2.w += v2 * x2.w;
            a3.x += v3 * x3.x; a3.y += v3 * x3.y;
            a3.z += v3 * x3.z; a3.w += v3 * x3.w;
        }
        for (; j < cnt; j++) {
            int   c0 = __shfl_sync(0xffffffffu, p.x, j);
            float v0 = __int_as_float(__shfl_sync(0xffffffffu, p.y, j));
            float4 x0 = x4[(long long)c0 * F4 + lane];
            a0.x += v0 * x0.x; a0.y += v0 * x0.y;
            a0.z += v0 * x0.z; a0.w += v0 * x0.w;
        }
    }
    float inv = 1.f / fmaxf((float)(tEnd - s), 1.f);
    float4 acc = make_float4((a0.x + a1.x + a2.x + a3.x) * inv,
                             (a0.y + a1.y + a2.y + a3.y) * inv,
                             (a0.z + a1.z + a2.z + a3.z) * inv,
                             (a0.w + a1.w + a2.w + a3.w) * inv);
    g_agg[(long long)nid * F4 + lane] = acc;
}

// ---------------------------------------------------------------------------
// Kernel 7: PERSISTENT fused  out = relu( agg @ Wl^T + b + x @ Wr^T )
//   [R7-champion body, unchanged]
// ---------------------------------------------------------------------------
__global__ __launch_bounds__(256, 1)
void gemm_kernel(const float4* __restrict__ x4,
                 const float*  __restrict__ Wl,
                 const float*  __restrict__ Wr,
                 const float*  __restrict__ bl,
                 float*        __restrict__ out,
                 int n_nodes, int ntiles) {
    extern __shared__ float2 sm2[];
    float2* wpair = sm2;               // [k][j] {wl, wr}  128*128
    float2* axs   = wpair + F * F;     // [r][k] {agg, x}   64*128

    const int t = threadIdx.x;

    // W fill once: consecutive threads -> consecutive j => conflict-free STS.
    for (int i = t; i < F * F; i += 256) {
        int j = i & 127;
        int k = i >> 7;
        wpair[k * F + j] = make_float2(Wl[j * F + k], Wr[j * F + k]);
    }

    const int wid  = t >> 5;
    const int lane = t & 31;
    const int i0   = wid * 8;
    const int j0   = lane * 4;
    const float4 bv = *(const float4*)&bl[j0];

    // register staging for one tile: 8 (agg,x) float4 pairs per thread
    float4 pa[8], px[8];

    // prefetch first tile
    {
        int tile = blockIdx.x;
#pragma unroll
        for (int u = 0; u < 8; u++) {
            int idx = t + u * 256;               // < 2048 = BM*F4
            int gi  = tile * BM + (idx >> 5);
            int c4  = idx & 31;
            bool ok = (tile < ntiles) && (gi < n_nodes);
            pa[u] = ok ? g_agg[(long long)gi * F4 + c4]
                       : make_float4(0.f, 0.f, 0.f, 0.f);
            px[u] = ok ? x4[(long long)gi * F4 + c4]
                       : make_float4(0.f, 0.f, 0.f, 0.f);
        }
    }

    for (int tile = blockIdx.x; tile < ntiles; tile += gridDim.x) {
        __syncthreads();          // axs free (prev tile's readers done); W ready
        // STS staged tile
#pragma unroll
        for (int u = 0; u < 8; u++) {
            int idx = t + u * 256;
            int r   = idx >> 5;
            int c4  = idx & 31;
            float2* dst = &axs[r * F + c4 * 4];
            dst[0] = make_float2(pa[u].x, px[u].x);
            dst[1] = make_float2(pa[u].y, px[u].y);
            dst[2] = make_float2(pa[u].z, px[u].z);
            dst[3] = make_float2(pa[u].w, px[u].w);
        }
        __syncthreads();

        // prefetch NEXT tile (LDGs overlap with compute below)
        {
            int nt = tile + gridDim.x;
#pragma unroll
            for (int u = 0; u < 8; u++) {
                int idx = t + u * 256;
                int gi  = nt * BM + (idx >> 5);
                int c4  = idx & 31;
                bool ok = (nt < ntiles) && (gi < n_nodes);
                pa[u] = ok ? g_agg[(long long)gi * F4 + c4]
                           : make_float4(0.f, 0.f, 0.f, 0.f);
                px[u] = ok ? x4[(long long)gi * F4 + c4]
                           : make_float4(0.f, 0.f, 0.f, 0.f);
            }
        }

        // compute 64x128 tile
        unsigned long long acc[8][4];
#pragma unroll
        for (int r = 0; r < 8; r++) {
            acc[r][0] = pack2(bv.x, 0.f);
            acc[r][1] = pack2(bv.y, 0.f);
            acc[r][2] = pack2(bv.z, 0.f);
            acc[r][3] = pack2(bv.w, 0.f);
        }

#pragma unroll 4
        for (int k = 0; k < F; k++) {
            ulonglong2 wa = *(const ulonglong2*)&wpair[k * F + j0];
            ulonglong2 wb = *(const ulonglong2*)&wpair[k * F + j0 + 2];
#pragma unroll
            for (int r = 0; r < 8; r++) {
                unsigned long long ax =
                    *(const unsigned long long*)&axs[(i0 + r) * F + k];
                fma2(acc[r][0], ax, wa.x);
                fma2(acc[r][1], ax, wa.y);
                fma2(acc[r][2], ax, wb.x);
                fma2(acc[r][3], ax, wb.y);
            }
        }

        int row0 = tile * BM;
#pragma unroll
        for (int r = 0; r < 8; r++) {
            int gi = row0 + i0 + r;
            if (gi < n_nodes) {
                float2 c0 = unpack2(acc[r][0]);
                float2 c1 = unpack2(acc[r][1]);
                float2 c2 = unpack2(acc[r][2]);
                float2 c3 = unpack2(acc[r][3]);
                float4 o;
                o.x = fmaxf(c0.x + c0.y, 0.f);
                o.y = fmaxf(c1.x + c1.y, 0.f);
                o.z = fmaxf(c2.x + c2.y, 0.f);
                o.w = fmaxf(c3.x + c3.y, 0.f);
                *(float4*)&out[(long long)gi * F + j0] = o;
            }
        }
    }
}

// ---------------------------------------------------------------------------
// Launch
// ---------------------------------------------------------------------------
extern "C" void kernel_launch(void* const* d_in, const int* in_sizes, int n_in,
                              void* d_out, int out_size) {
    const float* x   = (const float*)d_in[0];
    const float* val = (const float*)d_in[1];
    const float* Wl  = (const float*)d_in[2];
    const float* bl  = (const float*)d_in[3];
    const float* Wr  = (const float*)d_in[4];
    const int*   row = (const int*)d_in[5];
    const int*   col = (const int*)d_in[6];
    float*       out = (float*)d_out;

    const int n_nodes = in_sizes[0] / F;
    const int E       = in_sizes[1];
    const int nb      = (n_nodes + SCAN_BLK - 1) / SCAN_BLK;
    const int epairs  = (E + 1) / 2;

    // CSR build
    zero_cnt_kernel<<<(n_nodes + 255) / 256, 256>>>(n_nodes);
    count_kernel<<<(epairs + 511) / 512, 512>>>(row, E);
    scan1_kernel<<<nb, SCAN_BLK>>>(n_nodes);
    scan2_kernel<<<1, SCAN_BLK>>>(nb);
    scan3_kernel<<<nb, SCAN_BLK>>>(n_nodes, E);
    bucket_kernel<<<(epairs + 511) / 512, 512>>>(row, col, val, E);

    // gather-side aggregation (warp per node, 4-way MLP)
    aggregate_kernel<<<(n_nodes * 32 + 255) / 256, 256>>>((const float4*)x, n_nodes);

    // persistent fused GEMM + bias + relu (packed f32x2)
    static const size_t smem_bytes = (size_t)(F * F + BM * F) * sizeof(float2);
    cudaFuncSetAttribute(gemm_kernel, cudaFuncAttributeMaxDynamicSharedMemorySize,
                         (int)smem_bytes);
    int ntiles = (n_nodes + BM - 1) / BM;
    gemm_kernel<<<NSM, 256, smem_bytes>>>((const float4*)x, Wl, Wr, bl, out,
                                          n_nodes, ntiles);
}

// round 16
// speedup vs baseline: 1.0645x; 1.0645x over previous
#include <cuda_runtime.h>
#include <cuda_bf16.h>

#define F        128
#define F4       32          // F/4
#define NMAX     100000
#define EMAX     1600000
#define BM       64          // rows per GEMM tile
#define NSM      148
#define SCAN_BLK 1024
#define NBMAX    ((NMAX + SCAN_BLK - 1) / SCAN_BLK)

// Scratch (allocation-free rule: device globals are the sanctioned path)
__device__ float4 g_agg[NMAX * F4];          // aggregate (pre-divided by deg)
__device__ int    g_cnt[NMAX];               // degree counters
__device__ int    g_rowptr[NMAX + 1];        // CSR row pointers
__device__ int    g_woff[NMAX];              // working offsets for bucket scatter
__device__ int    g_bsum[NBMAX];             // scan block sums
__device__ int2   g_epair[EMAX];             // CSR-ordered {col, val_bits}

// packed f32x2 helpers (Blackwell FFMA2)
__device__ __forceinline__ void fma2(unsigned long long& d,
                                     unsigned long long a,
                                     unsigned long long b) {
    asm("fma.rn.f32x2 %0, %1, %2, %0;" : "+l"(d) : "l"(a), "l"(b));
}
__device__ __forceinline__ unsigned long long pack2(float lo, float hi) {
    unsigned long long u;
    asm("mov.b64 %0, {%1, %2};" : "=l"(u) : "f"(lo), "f"(hi));
    return u;
}
__device__ __forceinline__ float2 unpack2(unsigned long long u) {
    float lo, hi;
    asm("mov.b64 {%0, %1}, %2;" : "=f"(lo), "=f"(hi) : "l"(u));
    return make_float2(lo, hi);
}

// ---------------------------------------------------------------------------
// Kernel 0: zero the degree counters
// ---------------------------------------------------------------------------
__global__ void zero_cnt_kernel(int n_nodes) {
    int i = blockIdx.x * blockDim.x + threadIdx.x;
    if (i < n_nodes) g_cnt[i] = 0;
}

// ---------------------------------------------------------------------------
// Kernel 1: count degrees
// ---------------------------------------------------------------------------
__global__ void count_kernel(const int* __restrict__ row, int E) {
    int e = blockIdx.x * blockDim.x + threadIdx.x;
    if (e < E) atomicAdd(&g_cnt[row[e]], 1);
}

// ---------------------------------------------------------------------------
// Kernels 2-4: exclusive scan of degrees -> row_ptr (3-stage)
// ---------------------------------------------------------------------------
__global__ void scan1_kernel(int n_nodes) {
    __shared__ int sh[SCAN_BLK];
    int gi = blockIdx.x * SCAN_BLK + threadIdx.x;
    int v  = (gi < n_nodes) ? g_cnt[gi] : 0;
    sh[threadIdx.x] = v;
    __syncthreads();
#pragma unroll
    for (int off = 1; off < SCAN_BLK; off <<= 1) {
        int t = (threadIdx.x >= off) ? sh[threadIdx.x - off] : 0;
        __syncthreads();
        sh[threadIdx.x] += t;
        __syncthreads();
    }
    if (gi < n_nodes) g_cnt[gi] = sh[threadIdx.x] - v;       // exclusive within block
    if (threadIdx.x == SCAN_BLK - 1) g_bsum[blockIdx.x] = sh[threadIdx.x];
}

__global__ void scan2_kernel(int nb) {                        // one block, nb <= 1024
    __shared__ int sh[SCAN_BLK];
    int v = (threadIdx.x < nb) ? g_bsum[threadIdx.x] : 0;
    sh[threadIdx.x] = v;
    __syncthreads();
#pragma unroll
    for (int off = 1; off < SCAN_BLK; off <<= 1) {
        int t = (threadIdx.x >= off) ? sh[threadIdx.x - off] : 0;
        __syncthreads();
        sh[threadIdx.x] += t;
        __syncthreads();
    }
    if (threadIdx.x < nb) g_bsum[threadIdx.x] = sh[threadIdx.x] - v;  // exclusive
}

__global__ void scan3_kernel(int n_nodes, int E) {
    int gi = blockIdx.x * SCAN_BLK + threadIdx.x;
    if (gi < n_nodes) {
        int r = g_cnt[gi] + g_bsum[blockIdx.x];
        g_rowptr[gi] = r;
        g_woff[gi]   = r;
    }
    if (gi == 0) g_rowptr[n_nodes] = E;
}

// ---------------------------------------------------------------------------
// Kernel 5: bucket-permute {col, val} into CSR order
// ---------------------------------------------------------------------------
__global__ void bucket_kernel(const int*   __restrict__ row,
                              const int*   __restrict__ col,
                              const float* __restrict__ val,
                              int E) {
    int e = blockIdx.x * blockDim.x + threadIdx.x;
    if (e >= E) return;
    int r   = row[e];
    int pos = atomicAdd(&g_woff[r], 1);
    g_epair[pos] = make_int2(col[e], __float_as_int(val[e]));
}

// ---------------------------------------------------------------------------
// Kernel 6: warp-per-node gather aggregate, 2-way unrolled (MLP=2)
//   [R7-proven body, unchanged — local optimum of warps x MLP]
// ---------------------------------------------------------------------------
__global__ void aggregate_kernel(const float4* __restrict__ x4, int n_nodes) {
    int nid  = (blockIdx.x * blockDim.x + threadIdx.x) >> 5;
    int lane = threadIdx.x & 31;
    if (nid >= n_nodes) return;

    int s    = g_rowptr[nid];
    int tEnd = g_rowptr[nid + 1];

    float4 a0 = make_float4(0.f, 0.f, 0.f, 0.f);
    float4 a1 = make_float4(0.f, 0.f, 0.f, 0.f);

    for (int base = s; base < tEnd; base += 32) {
        int e = base + lane;
        int2 p = (e < tEnd) ? g_epair[e] : make_int2(0, 0);
        int cnt = min(32, tEnd - base);
        int j = 0;
        for (; j + 2 <= cnt; j += 2) {
            int   c0 = __shfl_sync(0xffffffffu, p.x, j);
            float v0 = __int_as_float(__shfl_sync(0xffffffffu, p.y, j));
            int   c1 = __shfl_sync(0xffffffffu, p.x, j + 1);
            float v1 = __int_as_float(__shfl_sync(0xffffffffu, p.y, j + 1));
            float4 x0 = x4[(long long)c0 * F4 + lane];
            float4 x1 = x4[(long long)c1 * F4 + lane];
            a0.x += v0 * x0.x; a0.y += v0 * x0.y;
            a0.z += v0 * x0.z; a0.w += v0 * x0.w;
            a1.x += v1 * x1.x; a1.y += v1 * x1.y;
            a1.z += v1 * x1.z; a1.w += v1 * x1.w;
        }
        if (j < cnt) {
            int   c0 = __shfl_sync(0xffffffffu, p.x, j);
            float v0 = __int_as_float(__shfl_sync(0xffffffffu, p.y, j));
            float4 x0 = x4[(long long)c0 * F4 + lane];
            a0.x += v0 * x0.x; a0.y += v0 * x0.y;
            a0.z += v0 * x0.z; a0.w += v0 * x0.w;
        }
    }
    float inv = 1.f / fmaxf((float)(tEnd - s), 1.f);
    float4 acc = make_float4((a0.x + a1.x) * inv, (a0.y + a1.y) * inv,
                             (a0.z + a1.z) * inv, (a0.w + a1.w) * inv);
    g_agg[(long long)nid * F4 + lane] = acc;
}

// ---------------------------------------------------------------------------
// Kernel 7: PERSISTENT fused  out = relu( agg @ Wl^T + b + x @ Wr^T )
//   [R7 structure; k-loop stepped by 2 with LDS.128 broadcast ax loads:
//    LDS cost 128 -> 96 cyc/k per SM, leaving FFMA2 as sole binder]
// ---------------------------------------------------------------------------
__global__ __launch_bounds__(256, 1)
void gemm_kernel(const float4* __restrict__ x4,
                 const float*  __restrict__ Wl,
                 const float*  __restrict__ Wr,
                 const float*  __restrict__ bl,
                 float*        __restrict__ out,
                 int n_nodes, int ntiles) {
    extern __shared__ float2 sm2[];
    float2* wpair = sm2;               // [k][j] {wl, wr}  128*128
    float2* axs   = wpair + F * F;     // [r][k] {agg, x}   64*128

    const int t = threadIdx.x;

    // W fill once: consecutive threads -> consecutive j => conflict-free STS.
    for (int i = t; i < F * F; i += 256) {
        int j = i & 127;
        int k = i >> 7;
        wpair[k * F + j] = make_float2(Wl[j * F + k], Wr[j * F + k]);
    }

    const int wid  = t >> 5;
    const int lane = t & 31;
    const int i0   = wid * 8;
    const int j0   = lane * 4;
    const float4 bv = *(const float4*)&bl[j0];

    // register staging for one tile: 8 (agg,x) float4 pairs per thread
    float4 pa[8], px[8];

    // prefetch first tile
    {
        int tile = blockIdx.x;
#pragma unroll
        for (int u = 0; u < 8; u++) {
            int idx = t + u * 256;               // < 2048 = BM*F4
            int gi  = tile * BM + (idx >> 5);
            int c4  = idx & 31;
            bool ok = (tile < ntiles) && (gi < n_nodes);
            pa[u] = ok ? g_agg[(long long)gi * F4 + c4]
                       : make_float4(0.f, 0.f, 0.f, 0.f);
            px[u] = ok ? x4[(long long)gi * F4 + c4]
                       : make_float4(0.f, 0.f, 0.f, 0.f);
        }
    }

    for (int tile = blockIdx.x; tile < ntiles; tile += gridDim.x) {
        __syncthreads();          // axs free (prev tile's readers done); W ready
        // STS staged tile
#pragma unroll
        for (int u = 0; u < 8; u++) {
            int idx = t + u * 256;
            int r   = idx >> 5;
            int c4  = idx & 31;
            float2* dst = &axs[r * F + c4 * 4];
            dst[0] = make_float2(pa[u].x, px[u].x);
            dst[1] = make_float2(pa[u].y, px[u].y);
            dst[2] = make_float2(pa[u].z, px[u].z);
            dst[3] = make_float2(pa[u].w, px[u].w);
        }
        __syncthreads();

        // prefetch NEXT tile (LDGs overlap with compute below)
        {
            int nt = tile + gridDim.x;
#pragma unroll
            for (int u = 0; u < 8; u++) {
                int idx = t + u * 256;
                int gi  = nt * BM + (idx >> 5);
                int c4  = idx & 31;
                bool ok = (nt < ntiles) && (gi < n_nodes);
                pa[u] = ok ? g_agg[(long long)gi * F4 + c4]
                           : make_float4(0.f, 0.f, 0.f, 0.f);
                px[u] = ok ? x4[(long long)gi * F4 + c4]
                           : make_float4(0.f, 0.f, 0.f, 0.f);
            }
        }

        // compute 64x128 tile  (k stepped by 2; ax via one LDS.128 broadcast)
        unsigned long long acc[8][4];
#pragma unroll
        for (int r = 0; r < 8; r++) {
            acc[r][0] = pack2(bv.x, 0.f);
            acc[r][1] = pack2(bv.y, 0.f);
            acc[r][2] = pack2(bv.z, 0.f);
            acc[r][3] = pack2(bv.w, 0.f);
        }

#pragma unroll 2
        for (int k = 0; k < F; k += 2) {
            ulonglong2 wa0 = *(const ulonglong2*)&wpair[k * F + j0];
            ulonglong2 wb0 = *(const ulonglong2*)&wpair[k * F + j0 + 2];
            ulonglong2 wa1 = *(const ulonglong2*)&wpair[(k + 1) * F + j0];
            ulonglong2 wb1 = *(const ulonglong2*)&wpair[(k + 1) * F + j0 + 2];
#pragma unroll
            for (int r = 0; r < 8; r++) {
                ulonglong2 ax2 =
                    *(const ulonglong2*)&axs[(i0 + r) * F + k];  // broadcast 16B
                fma2(acc[r][0], ax2.x, wa0.x);
                fma2(acc[r][1], ax2.x, wa0.y);
                fma2(acc[r][2], ax2.x, wb0.x);
                fma2(acc[r][3], ax2.x, wb0.y);
                fma2(acc[r][0], ax2.y, wa1.x);
                fma2(acc[r][1], ax2.y, wa1.y);
                fma2(acc[r][2], ax2.y, wb1.x);
                fma2(acc[r][3], ax2.y, wb1.y);
            }
        }

        int row0 = tile * BM;
#pragma unroll
        for (int r = 0; r < 8; r++) {
            int gi = row0 + i0 + r;
            if (gi < n_nodes) {
                float2 c0 = unpack2(acc[r][0]);
                float2 c1 = unpack2(acc[r][1]);
                float2 c2 = unpack2(acc[r][2]);
                float2 c3 = unpack2(acc[r][3]);
                float4 o;
                o.x = fmaxf(c0.x + c0.y, 0.f);
                o.y = fmaxf(c1.x + c1.y, 0.f);
                o.z = fmaxf(c2.x + c2.y, 0.f);
                o.w = fmaxf(c3.x + c3.y, 0.f);
                *(float4*)&out[(long long)gi * F + j0] = o;
            }
        }
    }
}

// ---------------------------------------------------------------------------
// Launch
// ---------------------------------------------------------------------------
extern "C" void kernel_launch(void* const* d_in, const int* in_sizes, int n_in,
                              void* d_out, int out_size) {
    const float* x   = (const float*)d_in[0];
    const float* val = (const float*)d_in[1];
    const float* Wl  = (const float*)d_in[2];
    const float* bl  = (const float*)d_in[3];
    const float* Wr  = (const float*)d_in[4];
    const int*   row = (const int*)d_in[5];
    const int*   col = (const int*)d_in[6];
    float*       out = (float*)d_out;

    const int n_nodes = in_sizes[0] / F;
    const int E       = in_sizes[1];
    const int nb      = (n_nodes + SCAN_BLK - 1) / SCAN_BLK;

    // CSR build
    zero_cnt_kernel<<<(n_nodes + 255) / 256, 256>>>(n_nodes);
    count_kernel<<<(E + 511) / 512, 512>>>(row, E);
    scan1_kernel<<<nb, SCAN_BLK>>>(n_nodes);
    scan2_kernel<<<1, SCAN_BLK>>>(nb);
    scan3_kernel<<<nb, SCAN_BLK>>>(n_nodes, E);
    bucket_kernel<<<(E + 511) / 512, 512>>>(row, col, val, E);

    // gather-side aggregation (warp per node)
    aggregate_kernel<<<(n_nodes * 32 + 255) / 256, 256>>>((const float4*)x, n_nodes);

    // persistent fused GEMM + bias + relu (packed f32x2)
    static const size_t smem_bytes = (size_t)(F * F + BM * F) * sizeof(float2);
    cudaFuncSetAttribute(gemm_kernel, cudaFuncAttributeMaxDynamicSharedMemorySize,
                         (int)smem_bytes);
    int ntiles = (n_nodes + BM - 1) / BM;
    gemm_kernel<<<NSM, 256, smem_bytes>>>((const float4*)x, Wl, Wr, bl, out,
                                          n_nodes, ntiles);
}